// round 15
// baseline (speedup 1.0000x reference)
#include <cuda_runtime.h>
#include <cuda_fp16.h>
#include <math.h>
#include <stdint.h>

#define NNODE 8000
#define DDIM  256
#define K3    768
#define EMAX  256000
#define LLAYERS 2
#define PRESERVE_F 0.1f
#define MAXNNZ (4 * NNODE)   // softmax rows sum to 1 => <=4 entries/row exceed 0.2

// ---------------- scratch (static device memory) ---------------------------------
__device__ float g_U [NNODE * DDIM];
__device__ float g_tmpD[NNODE * DDIM];
__device__ float g_tmpS[NNODE * DDIM];
__device__ float g_xw [NNODE * DDIM];
__device__ float g_xwS[NNODE * DDIM];
__device__ float g_Z2 [NNODE * DDIM];
__device__ float g_Z2c[NNODE * DDIM];
__device__ float g_Z2b[NNODE * DDIM];
__device__ float g_deg [NNODE];
__device__ float g_dis [NNODE];
__device__ float g_deg2[NNODE];
__device__ float g_dis2[NNODE];
__device__ float g_enorm[EMAX];
__device__ int   g_nnz;
__device__ int   g_sp_r[MAXNNZ];
__device__ int   g_sp_c[MAXNNZ];
__device__ float g_sp_v[MAXNNZ];
// fp16 2-way splits (x = h + l, ~22 mantissa bits)
__device__ __half g_X3h[NNODE * K3];
__device__ __half g_X3l[NNODE * K3];
__device__ __half g_Uh[NNODE * DDIM];
__device__ __half g_Ul[NNODE * DDIM];
__device__ __half g_tDh[NNODE * DDIM];
__device__ __half g_tDl[NNODE * DDIM];
__device__ __half g_tSh[NNODE * DDIM];
__device__ __half g_tSl[NNODE * DDIM];
__device__ __half g_Wfh[K3 * DDIM];
__device__ __half g_Wfl[K3 * DDIM];
__device__ __half g_W0h[LLAYERS * DDIM * DDIM];
__device__ __half g_W0l[LLAYERS * DDIM * DDIM];
__device__ __half g_W1h[LLAYERS * DDIM * DDIM];
__device__ __half g_W1l[LLAYERS * DDIM * DDIM];

__device__ __forceinline__ uint32_t smem_u32(const void* p) {
    uint32_t a;
    asm("{ .reg .u64 t; cvta.to.shared.u64 t, %1; cvt.u32.u64 %0, t; }" : "=r"(a) : "l"(p));
    return a;
}

__device__ __forceinline__ void red_add_v4(float* addr, float4 v) {
    asm volatile("red.global.add.v4.f32 [%0], {%1,%2,%3,%4};"
                 :: "l"(addr), "f"(v.x), "f"(v.y), "f"(v.z), "f"(v.w) : "memory");
}

#define LDSM_X4(r0, r1, r2, r3, addr) \
    asm volatile("ldmatrix.sync.aligned.m8n8.x4.shared.b16 {%0,%1,%2,%3}, [%4];" \
                 : "=r"(r0), "=r"(r1), "=r"(r2), "=r"(r3) : "r"(addr))
#define LDSM_X2(r0, r1, addr) \
    asm volatile("ldmatrix.sync.aligned.m8n8.x2.shared.b16 {%0,%1}, [%2];" \
                 : "=r"(r0), "=r"(r1) : "r"(addr))
#define LDSM_X2_T(r0, r1, addr) \
    asm volatile("ldmatrix.sync.aligned.m8n8.x2.trans.shared.b16 {%0,%1}, [%2];" \
                 : "=r"(r0), "=r"(r1) : "r"(addr))
#define MMA_F16(c, a0, a1, a2, a3, b0, b1) \
    asm volatile("mma.sync.aligned.m16n8k16.row.col.f32.f16.f16.f32 " \
                 "{%0,%1,%2,%3}, {%4,%5,%6,%7}, {%8,%9}, {%0,%1,%2,%3};" \
                 : "+f"((c)[0]), "+f"((c)[1]), "+f"((c)[2]), "+f"((c)[3]) \
                 : "r"(a0), "r"(a1), "r"(a2), "r"(a3), "r"(b0), "r"(b1))
#define CP_ASYNC16(saddr, gptr, sz) \
    asm volatile("cp.async.cg.shared.global [%0], [%1], 16, %2;" \
                 :: "r"(saddr), "l"(gptr), "r"(sz))
#define CP_COMMIT() asm volatile("cp.async.commit_group;")
#define CP_WAIT1()  asm volatile("cp.async.wait_group 1;")
#define CP_WAIT0()  asm volatile("cp.async.wait_group 0;")

#define LDT 40
#define LDB 136

// =================== syrk: C = U @ U^T (fp16 2-split, 2-stage, 2 CTA/SM) =========
#define SYRK_TILE_ELEMS (128 * LDT)
#define SYRK_STAGE_ELEMS (4 * SYRK_TILE_ELEMS)
#define SYRK_SMEM_DYN (2 * SYRK_STAGE_ELEMS * 2)

__global__ __launch_bounds__(256, 2)
void syrk_mma_kernel(const __half* __restrict__ Uh,
                     const __half* __restrict__ Ul,
                     float* __restrict__ C, int n)
{
    extern __shared__ char smem[];
    __half* tiles = (__half*)smem;
    float* epi = (float*)smem;

    const int tid  = threadIdx.x;
    const int wid  = tid >> 5;
    const int lane = tid & 31;
    const int wm   = wid & 1;
    const int wn   = wid >> 1;
    const int group = lane >> 2;
    const int tig   = lane & 3;

    int t = blockIdx.x;
    int bi = (int)((sqrtf(8.0f * (float)t + 1.0f) - 1.0f) * 0.5f);
    while ((bi + 1) * (bi + 2) / 2 <= t) bi++;
    while (bi * (bi + 1) / 2 > t) bi--;
    int bj = t - bi * (bi + 1) / 2;
    const int m0 = bi * 128;
    const int n0 = bj * 128;

    float acc[4][4][4];
#pragma unroll
    for (int a = 0; a < 4; a++)
#pragma unroll
        for (int b = 0; b < 4; b++)
#pragma unroll
            for (int c = 0; c < 4; c++) acc[a][b][c] = 0.f;

    const __half* srcs[4] = { Uh, Ul, Uh, Ul };
    const uint32_t sT = smem_u32(tiles);

    const int a_row = (lane & 15);
    const int a_col = (lane >> 4) * 8;
    const int b_row = (lane & 7);
    const int b_col = ((lane >> 3) & 1) * 8;
    const uint32_t a_base = (uint32_t)((wm * 64 + a_row) * LDT + a_col) * 2;
    const uint32_t b_base = (uint32_t)((wn * 32 + b_row) * LDT + b_col) * 2;

    auto load_chunk = [&](int k0, int stage) {
        uint32_t dst0 = sT + (uint32_t)(stage * SYRK_STAGE_ELEMS) * 2;
#pragma unroll
        for (int s = 0; s < 4; s++) {
            const __half* src = srcs[s];
            const int rowbase = (s < 2) ? m0 : n0;
            uint32_t dts = dst0 + (uint32_t)(s * SYRK_TILE_ELEMS) * 2;
#pragma unroll
            for (int it = 0; it < 2; it++) {
                int lin = it * 256 + tid;
                int r   = lin >> 2;
                int c8  = (lin & 3) * 8;
                int g   = rowbase + r;
                uint32_t sz = (g < n) ? 16u : 0u;
                int g2 = (g < n) ? g : 0;
                const __half* gp = src + (size_t)g2 * DDIM + k0 + c8;
                CP_ASYNC16(dts + (uint32_t)(r * LDT + c8) * 2, gp, sz);
            }
        }
    };

    load_chunk(0, 0);
    CP_COMMIT();

#pragma unroll 1
    for (int kc = 0; kc < 8; kc++) {
        const int cur = kc & 1;
        if (kc + 1 < 8) {
            load_chunk((kc + 1) * 32, cur ^ 1);
            CP_COMMIT();
            CP_WAIT1();
        } else {
            CP_WAIT0();
        }
        __syncthreads();

        const uint32_t stg = sT + (uint32_t)(cur * SYRK_STAGE_ELEMS) * 2;
        const uint32_t sAh = stg;
        const uint32_t sAl = stg + SYRK_TILE_ELEMS * 2u;
        const uint32_t sBh = stg + SYRK_TILE_ELEMS * 4u;
        const uint32_t sBl = stg + SYRK_TILE_ELEMS * 6u;

#pragma unroll
        for (int ks = 0; ks < 2; ks++) {
            const uint32_t koff = (uint32_t)(ks * 16) * 2;
            uint32_t ah[4][4], bh[4][2];
#pragma unroll
            for (int mt = 0; mt < 4; mt++)
                LDSM_X4(ah[mt][0], ah[mt][1], ah[mt][2], ah[mt][3],
                        sAh + a_base + koff + (uint32_t)(mt * 16 * LDT) * 2);
#pragma unroll
            for (int nt = 0; nt < 4; nt++)
                LDSM_X2(bh[nt][0], bh[nt][1],
                        sBh + b_base + koff + (uint32_t)(nt * 8 * LDT) * 2);
#pragma unroll
            for (int mt = 0; mt < 4; mt++)
#pragma unroll
                for (int nt = 0; nt < 4; nt++)
                    MMA_F16(acc[mt][nt], ah[mt][0], ah[mt][1], ah[mt][2], ah[mt][3],
                            bh[nt][0], bh[nt][1]);
            {
                uint32_t bl[4][2];
#pragma unroll
                for (int nt = 0; nt < 4; nt++)
                    LDSM_X2(bl[nt][0], bl[nt][1],
                            sBl + b_base + koff + (uint32_t)(nt * 8 * LDT) * 2);
#pragma unroll
                for (int mt = 0; mt < 4; mt++)
#pragma unroll
                    for (int nt = 0; nt < 4; nt++)
                        MMA_F16(acc[mt][nt], ah[mt][0], ah[mt][1], ah[mt][2], ah[mt][3],
                                bl[nt][0], bl[nt][1]);
            }
            {
                uint32_t al[4][4];
#pragma unroll
                for (int mt = 0; mt < 4; mt++)
                    LDSM_X4(al[mt][0], al[mt][1], al[mt][2], al[mt][3],
                            sAl + a_base + koff + (uint32_t)(mt * 16 * LDT) * 2);
#pragma unroll
                for (int mt = 0; mt < 4; mt++)
#pragma unroll
                    for (int nt = 0; nt < 4; nt++)
                        MMA_F16(acc[mt][nt], al[mt][0], al[mt][1], al[mt][2], al[mt][3],
                                bh[nt][0], bh[nt][1]);
            }
        }
        __syncthreads();
    }

    // direct write
#pragma unroll
    for (int mt = 0; mt < 4; mt++) {
#pragma unroll
        for (int nt = 0; nt < 4; nt++) {
            int lm = wm * 64 + mt * 16 + group;
            int ln = wn * 32 + nt * 8 + tig * 2;
            int gm = m0 + lm, gn = n0 + ln;
            if (gn + 1 < n) {
                if (gm < n)
                    *reinterpret_cast<float2*>(C + (size_t)gm * n + gn) =
                        make_float2(acc[mt][nt][0], acc[mt][nt][1]);
                if (gm + 8 < n)
                    *reinterpret_cast<float2*>(C + (size_t)(gm + 8) * n + gn) =
                        make_float2(acc[mt][nt][2], acc[mt][nt][3]);
            }
        }
    }

    // mirrored write via smem transpose
    if (bi != bj) {
        __syncthreads();
#pragma unroll
        for (int mt = 0; mt < 4; mt++) {
#pragma unroll
            for (int nt = 0; nt < 4; nt++) {
                int lm = wm * 64 + mt * 16 + group;
                int ln = wn * 32 + nt * 8 + tig * 2;
                epi[lm * 129 + ln]           = acc[mt][nt][0];
                epi[lm * 129 + ln + 1]       = acc[mt][nt][1];
                epi[(lm + 8) * 129 + ln]     = acc[mt][nt][2];
                epi[(lm + 8) * 129 + ln + 1] = acc[mt][nt][3];
            }
        }
        __syncthreads();
        const int c_row = tid >> 1;
        const int half  = tid & 1;
        const int grow  = n0 + c_row;
        if (grow < n) {
            float* outrow = C + (size_t)grow * n;
#pragma unroll
            for (int i = 0; i < 16; i++) {
                int ml = half * 64 + i * 4;
                if (m0 + ml + 3 < n) {
                    float4 v = make_float4(epi[(ml + 0) * 129 + c_row],
                                           epi[(ml + 1) * 129 + c_row],
                                           epi[(ml + 2) * 129 + c_row],
                                           epi[(ml + 3) * 129 + c_row]);
                    *reinterpret_cast<float4*>(outrow + m0 + ml) = v;
                } else {
                    for (int q = 0; q < 4; q++)
                        if (m0 + ml + q < n)
                            outrow[m0 + ml + q] = epi[(ml + q) * 129 + c_row];
                }
            }
        }
    }
}

// =================== GEMM: C = A @ B (+bias), fp16 2-split, 2-stage ==============
#define GEMM_AT_ELEMS (128 * LDT)
#define GEMM_BT_ELEMS (32 * LDB)
#define GEMM_STAGE_ELEMS (2 * (GEMM_AT_ELEMS + GEMM_BT_ELEMS))
#define GEMM_SMEM_DYN (2 * GEMM_STAGE_ELEMS * 2)

template<bool BIAS>
__global__ __launch_bounds__(256, 2)
void gemm_mma_kernel(const __half* __restrict__ Ah_,
                     const __half* __restrict__ Al_,
                     const __half* __restrict__ Bh_,
                     const __half* __restrict__ Bl_,
                     float* __restrict__ C, const float* __restrict__ bias,
                     int M, int N, int K)
{
    extern __shared__ char smem[];
    __half* tiles = (__half*)smem;

    const int tid  = threadIdx.x;
    const int wid  = tid >> 5;
    const int lane = tid & 31;
    const int wm   = wid & 1;
    const int wn   = wid >> 1;
    const int group = lane >> 2;
    const int tig   = lane & 3;

    const int n0 = blockIdx.x * 128;
    const int m0 = blockIdx.y * 128;

    float acc[4][4][4];
#pragma unroll
    for (int a = 0; a < 4; a++)
#pragma unroll
        for (int b = 0; b < 4; b++)
#pragma unroll
            for (int c = 0; c < 4; c++) acc[a][b][c] = 0.f;

    const __half* Asrc[2] = { Ah_, Al_ };
    const __half* Bsrc[2] = { Bh_, Bl_ };
    const uint32_t sT = smem_u32(tiles);

    const int a_row = (lane & 15);
    const int a_col = (lane >> 4) * 8;
    const uint32_t a_base = (uint32_t)((wm * 64 + a_row) * LDT + a_col) * 2;
    const uint32_t bt_base = (uint32_t)((lane & 15) * LDB + wn * 32) * 2;

    auto load_chunk = [&](int k0, int stage) {
        uint32_t dst0 = sT + (uint32_t)(stage * GEMM_STAGE_ELEMS) * 2;
#pragma unroll
        for (int s = 0; s < 2; s++) {
            uint32_t dts = dst0 + (uint32_t)(s * GEMM_AT_ELEMS) * 2;
#pragma unroll
            for (int it = 0; it < 2; it++) {
                int lin = it * 256 + tid;
                int r   = lin >> 2;
                int c8  = (lin & 3) * 8;
                int g   = m0 + r;
                uint32_t sz = (g < M) ? 16u : 0u;
                int g2 = (g < M) ? g : 0;
                const __half* gp = Asrc[s] + (size_t)g2 * K + k0 + c8;
                CP_ASYNC16(dts + (uint32_t)(r * LDT + c8) * 2, gp, sz);
            }
        }
        uint32_t dstB = dst0 + (uint32_t)(2 * GEMM_AT_ELEMS) * 2;
#pragma unroll
        for (int s = 0; s < 2; s++) {
            uint32_t dts = dstB + (uint32_t)(s * GEMM_BT_ELEMS) * 2;
#pragma unroll
            for (int it = 0; it < 2; it++) {
                int lin = it * 256 + tid;
                int r   = lin >> 4;
                int c8  = (lin & 15) * 8;
                const __half* gp = Bsrc[s] + (size_t)(k0 + r) * N + n0 + c8;
                CP_ASYNC16(dts + (uint32_t)(r * LDB + c8) * 2, gp, 16u);
            }
        }
    };

    const int NC = K / 32;
    load_chunk(0, 0);
    CP_COMMIT();

#pragma unroll 1
    for (int kc = 0; kc < NC; kc++) {
        const int cur = kc & 1;
        if (kc + 1 < NC) {
            load_chunk((kc + 1) * 32, cur ^ 1);
            CP_COMMIT();
            CP_WAIT1();
        } else {
            CP_WAIT0();
        }
        __syncthreads();

        const uint32_t stg = sT + (uint32_t)(cur * GEMM_STAGE_ELEMS) * 2;
        const uint32_t sAh = stg;
        const uint32_t sAl = stg + GEMM_AT_ELEMS * 2u;
        const uint32_t sBh = stg + GEMM_AT_ELEMS * 4u;
        const uint32_t sBl = sBh + GEMM_BT_ELEMS * 2u;

#pragma unroll
        for (int ks = 0; ks < 2; ks++) {
            const uint32_t akoff = (uint32_t)(ks * 16) * 2;
            const uint32_t bkoff = (uint32_t)(ks * 16 * LDB) * 2;
            uint32_t ah[4][4], bh[4][2];
#pragma unroll
            for (int mt = 0; mt < 4; mt++)
                LDSM_X4(ah[mt][0], ah[mt][1], ah[mt][2], ah[mt][3],
                        sAh + a_base + akoff + (uint32_t)(mt * 16 * LDT) * 2);
#pragma unroll
            for (int nt = 0; nt < 4; nt++)
                LDSM_X2_T(bh[nt][0], bh[nt][1],
                          sBh + bt_base + bkoff + (uint32_t)(nt * 8) * 2);
#pragma unroll
            for (int mt = 0; mt < 4; mt++)
#pragma unroll
                for (int nt = 0; nt < 4; nt++)
                    MMA_F16(acc[mt][nt], ah[mt][0], ah[mt][1], ah[mt][2], ah[mt][3],
                            bh[nt][0], bh[nt][1]);
            {
                uint32_t bl[4][2];
#pragma unroll
                for (int nt = 0; nt < 4; nt++)
                    LDSM_X2_T(bl[nt][0], bl[nt][1],
                              sBl + bt_base + bkoff + (uint32_t)(nt * 8) * 2);
#pragma unroll
                for (int mt = 0; mt < 4; mt++)
#pragma unroll
                    for (int nt = 0; nt < 4; nt++)
                        MMA_F16(acc[mt][nt], ah[mt][0], ah[mt][1], ah[mt][2], ah[mt][3],
                                bl[nt][0], bl[nt][1]);
            }
            {
                uint32_t al[4][4];
#pragma unroll
                for (int mt = 0; mt < 4; mt++)
                    LDSM_X4(al[mt][0], al[mt][1], al[mt][2], al[mt][3],
                            sAl + a_base + akoff + (uint32_t)(mt * 16 * LDT) * 2);
#pragma unroll
                for (int mt = 0; mt < 4; mt++)
#pragma unroll
                    for (int nt = 0; nt < 4; nt++)
                        MMA_F16(acc[mt][nt], al[mt][0], al[mt][1], al[mt][2], al[mt][3],
                                bh[nt][0], bh[nt][1]);
            }
        }
        __syncthreads();
    }

    // epilogue
#pragma unroll
    for (int mt = 0; mt < 4; mt++) {
#pragma unroll
        for (int nt = 0; nt < 4; nt++) {
            int lm = wm * 64 + mt * 16 + group;
            int ln = wn * 32 + nt * 8 + tig * 2;
            int gm = m0 + lm, gn = n0 + ln;
            float b0 = 0.f, b1 = 0.f;
            if (BIAS) { b0 = bias[gn]; b1 = bias[gn + 1]; }
            if (gm < M)
                *reinterpret_cast<float2*>(C + (size_t)gm * N + gn) =
                    make_float2(acc[mt][nt][0] + b0, acc[mt][nt][1] + b1);
            if (gm + 8 < M)
                *reinterpret_cast<float2*>(C + (size_t)(gm + 8) * N + gn) =
                    make_float2(acc[mt][nt][2] + b0, acc[mt][nt][3] + b1);
        }
    }
}

// ---------------- split kernels (fp16 2-way) --------------------------------------
__global__ void split2h_kernel(const float* __restrict__ U,
                               __half* __restrict__ Uh,
                               __half* __restrict__ Ul, int total)
{
    int i = blockIdx.x * blockDim.x + threadIdx.x;
    if (i >= total) return;
    float x = U[i];
    __half h = __float2half(x);
    Uh[i] = h;
    Ul[i] = __float2half(x - __half2float(h));
}

__global__ void gather_split2_kernel(const float* __restrict__ emb1,
                                     const float* __restrict__ demand,
                                     const float* __restrict__ supply,
                                     __half* __restrict__ Xh,
                                     __half* __restrict__ Xl, int n, int T)
{
    int i = blockIdx.x * blockDim.x + threadIdx.x;
    int total = n * DDIM;
    if (i >= total) return;
    int node = i / DDIM, d = i % DDIM;
    float v[3];
    v[0] = emb1[(size_t)node * DDIM + d];
    v[1] = demand[((size_t)node * T + (T - 1)) * DDIM + d];
    v[2] = supply[((size_t)node * T + (T - 1)) * DDIM + d];
#pragma unroll
    for (int s = 0; s < 3; s++) {
        size_t idx = (size_t)node * K3 + s * DDIM + d;
        float x = v[s];
        __half h = __float2half(x);
        Xh[idx] = h;
        Xl[idx] = __float2half(x - __half2float(h));
    }
}

// ---------------- small kernels ---------------------------------------------------
__global__ void softmax_relu_kernel(float* __restrict__ Z, int n,
                                    int* __restrict__ nnz,
                                    int* __restrict__ sr, int* __restrict__ sc,
                                    float* __restrict__ sv,
                                    float* __restrict__ deg)
{
    __shared__ float row[NNODE];
    __shared__ float red[256];
    int r = blockIdx.x;
    int t = threadIdx.x;
    float* zr = Z + (size_t)r * n;
    const int n4 = n >> 2;

    float mx = -3.4e38f;
    for (int c4 = t; c4 < n4; c4 += 256) {
        float4 v = reinterpret_cast<const float4*>(zr)[c4];
        reinterpret_cast<float4*>(row)[c4] = v;
        mx = fmaxf(mx, fmaxf(fmaxf(v.x, v.y), fmaxf(v.z, v.w)));
    }
    for (int c = n4 * 4 + t; c < n; c += 256) { float v = zr[c]; row[c] = v; mx = fmaxf(mx, v); }
    red[t] = mx; __syncthreads();
    for (int s = 128; s > 0; s >>= 1) {
        if (t < s) red[t] = fmaxf(red[t], red[t + s]);
        __syncthreads();
    }
    mx = red[0];
    __syncthreads();

    float sm = 0.f;
    for (int c4 = t; c4 < n4; c4 += 256) {
        float4 v = reinterpret_cast<const float4*>(row)[c4];
        v.x = __expf(v.x - mx); v.y = __expf(v.y - mx);
        v.z = __expf(v.z - mx); v.w = __expf(v.w - mx);
        reinterpret_cast<float4*>(row)[c4] = v;
        sm += v.x + v.y + v.z + v.w;
    }
    for (int c = n4 * 4 + t; c < n; c += 256) { float e = __expf(row[c] - mx); row[c] = e; sm += e; }
    red[t] = sm; __syncthreads();
    for (int s = 128; s > 0; s >>= 1) {
        if (t < s) red[t] += red[t + s];
        __syncthreads();
    }
    float inv = 1.0f / red[0];
    for (int c4 = t; c4 < n4; c4 += 256) {
        float4 v = reinterpret_cast<const float4*>(row)[c4];
        float4 p;
        p.x = fmaxf(v.x * inv - 0.2f, 0.f);
        p.y = fmaxf(v.y * inv - 0.2f, 0.f);
        p.z = fmaxf(v.z * inv - 0.2f, 0.f);
        p.w = fmaxf(v.w * inv - 0.2f, 0.f);
        reinterpret_cast<float4*>(zr)[c4] = p;
        float pv[4] = { p.x, p.y, p.z, p.w };
#pragma unroll
        for (int q = 0; q < 4; q++) {
            if (pv[q] > 0.f) {
                int c = c4 * 4 + q;
                int idx = atomicAdd(nnz, 1);
                if (idx < MAXNNZ) { sr[idx] = r; sc[idx] = c; sv[idx] = pv[q]; }
                atomicAdd(&deg[c], pv[q]);
            }
        }
    }
    for (int c = n4 * 4 + t; c < n; c += 256) {
        float p = fmaxf(row[c] * inv - 0.2f, 0.f);
        zr[c] = p;
        if (p > 0.f) {
            int idx = atomicAdd(nnz, 1);
            if (idx < MAXNNZ) { sr[idx] = r; sc[idx] = c; sv[idx] = p; }
            atomicAdd(&deg[c], p);
        }
    }
}

__global__ void fill_kernel(float* p, float v, int n)
{
    int i = blockIdx.x * blockDim.x + threadIdx.x;
    if (i < n) p[i] = v;
}

__global__ void zero_int_kernel(int* p) { *p = 0; }

__global__ void rsqrt_kernel(float* __restrict__ dst, const float* __restrict__ src, int n)
{
    int i = blockIdx.x * blockDim.x + threadIdx.x;
    if (i < n) dst[i] = rsqrtf(src[i]);
}

__global__ void dense_scatter_kernel(const float* __restrict__ xw,
                                     const int* __restrict__ sr,
                                     const int* __restrict__ sc,
                                     const float* __restrict__ sv,
                                     const float* __restrict__ dis,
                                     float* __restrict__ agg,
                                     const int* __restrict__ nnz)
{
    int warp = (blockIdx.x * blockDim.x + threadIdx.x) >> 5;
    int lane = threadIdx.x & 31;
    int m = *nnz; if (m > MAXNNZ) m = MAXNNZ;
    if (warp >= m) return;
    int r = sr[warp], c = sc[warp];
    float w = sv[warp] * dis[r];
    const float4* xr = reinterpret_cast<const float4*>(xw + (size_t)r * DDIM);
    float* ar = agg + (size_t)c * DDIM;
#pragma unroll
    for (int h = 0; h < 2; h++) {
        int f4 = h * 32 + lane;
        float4 x = xr[f4];
        red_add_v4(ar + f4 * 4, make_float4(w * x.x, w * x.y, w * x.z, w * x.w));
    }
}

// dense combine, intermediate layer: temp (in-place) + fp16 split emission
__global__ void dense_combine_kernel(float* __restrict__ temp, const float* __restrict__ Z2,
                                     const float* __restrict__ xw, const float* __restrict__ dis,
                                     const float* __restrict__ b, int n, int d,
                                     __half* __restrict__ th,
                                     __half* __restrict__ tl)
{
    int i = blockIdx.x * blockDim.x + threadIdx.x;
    if (i >= n * d) return;
    int c = i / d, dd = i - c * d;
    float s = dis[c];
    float out = s * Z2[i] + s * s * xw[i] + b[dd];
    float v = (1.0f - PRESERVE_F) * out + PRESERVE_F * temp[i];
    temp[i] = v;
    __half h = __float2half(v);
    th[i] = h; tl[i] = __float2half(v - __half2float(h));
}

// dense combine, FINAL layer: fuse out_skill = v + tmpS
__global__ void dense_combine_add_kernel(const float* __restrict__ temp,
                                         const float* __restrict__ Z2,
                                         const float* __restrict__ xw,
                                         const float* __restrict__ dis,
                                         const float* __restrict__ b,
                                         const float* __restrict__ tmpS,
                                         float* __restrict__ out, int n, int d)
{
    int i = blockIdx.x * blockDim.x + threadIdx.x;
    if (i >= n * d) return;
    int c = i / d, dd = i - c * d;
    float s = dis[c];
    float o = s * Z2[i] + s * s * xw[i] + b[dd];
    float v = (1.0f - PRESERVE_F) * o + PRESERVE_F * temp[i];
    out[i] = v + tmpS[i];
}

__global__ void edge_deg_kernel(const int* __restrict__ dst, const float* __restrict__ attr,
                                float* __restrict__ deg2, int E)
{
    int e = blockIdx.x * blockDim.x + threadIdx.x;
    if (e < E) atomicAdd(&deg2[dst[e]], attr[e]);
}

__global__ void enorm_kernel(const int* __restrict__ src, const int* __restrict__ dst,
                             const float* __restrict__ attr, const float* __restrict__ dis2,
                             float* __restrict__ enorm, int E)
{
    int e = blockIdx.x * blockDim.x + threadIdx.x;
    if (e < E) enorm[e] = dis2[src[e]] * attr[e] * dis2[dst[e]];
}

__global__ void scatter_kernel(const float* __restrict__ xw, const int* __restrict__ src,
                               const int* __restrict__ dst, const float* __restrict__ enorm,
                               float* __restrict__ agg, int E, int d)
{
    int warp = (blockIdx.x * blockDim.x + threadIdx.x) >> 5;
    int lane = threadIdx.x & 31;
    if (warp >= E) return;
    int s = src[warp], t = dst[warp];
    float w = enorm[warp];
    const float4* xr = reinterpret_cast<const float4*>(xw + (size_t)s * DDIM);
    float* ar = agg + (size_t)t * DDIM;
#pragma unroll
    for (int h = 0; h < 2; h++) {
        int f4 = h * 32 + lane;
        float4 x = xr[f4];
        red_add_v4(ar + f4 * 4, make_float4(w * x.x, w * x.y, w * x.z, w * x.w));
    }
}

template<bool EMIT>
__global__ void sparse_combine_kernel(float* __restrict__ temp, const float* __restrict__ agg,
                                      const float* __restrict__ xw, const float* __restrict__ dis2,
                                      const float* __restrict__ b, int n, int d,
                                      __half* __restrict__ th,
                                      __half* __restrict__ tl)
{
    int i = blockIdx.x * blockDim.x + threadIdx.x;
    if (i >= n * d) return;
    int c = i / d, dd = i - c * d;
    float s = dis2[c];
    float out = agg[i] + s * s * xw[i] + b[dd];
    float v = (1.0f - PRESERVE_F) * out + PRESERVE_F * temp[i];
    temp[i] = v;
    if (EMIT) {
        __half h = __float2half(v);
        th[i] = h; tl[i] = __float2half(v - __half2float(h));
    }
}

// ---------------- host orchestration ----------------------------------------------
extern "C" void kernel_launch(void* const* d_in, const int* in_sizes, int n_in,
                              void* d_out, int out_size)
{
    const float* demand  = (const float*)d_in[0];
    const float* supply  = (const float*)d_in[1];
    const int*   eidx    = (const int*)  d_in[2];
    const float* eattr   = (const float*)d_in[3];
    const float* emb1    = (const float*)d_in[4];
    const float* fuse_W  = (const float*)d_in[5];
    const float* fuse_b  = (const float*)d_in[6];
    const float* gnn0_W  = (const float*)d_in[7];
    const float* gnn0_b  = (const float*)d_in[8];
    const float* gnn1_W  = (const float*)d_in[9];
    const float* gnn1_b  = (const float*)d_in[10];

    const int n = in_sizes[4] / DDIM;
    const int E = in_sizes[3];
    const int T = in_sizes[0] / (n * DDIM);

    float* out_emb1  = (float*)d_out;
    float* out_skill = out_emb1 + (size_t)n * DDIM;
    float* out_pred  = out_skill + (size_t)n * DDIM;

    float *pU, *ptD, *ptS, *pxw, *pxwS, *pZ2, *pZ2c, *pZ2b, *pdeg, *pdis, *pdeg2, *pdis2, *pen, *psv;
    int *pnnz, *psr, *psc;
    __half *pX3h, *pX3l, *pUh, *pUl, *ptDh, *ptDl, *ptSh, *ptSl;
    __half *pWfh, *pWfl, *pW0h, *pW0l, *pW1h, *pW1l;
    cudaGetSymbolAddress((void**)&pU,   g_U);
    cudaGetSymbolAddress((void**)&ptD,  g_tmpD);
    cudaGetSymbolAddress((void**)&ptS,  g_tmpS);
    cudaGetSymbolAddress((void**)&pxw,  g_xw);
    cudaGetSymbolAddress((void**)&pxwS, g_xwS);
    cudaGetSymbolAddress((void**)&pZ2,  g_Z2);
    cudaGetSymbolAddress((void**)&pZ2c, g_Z2c);
    cudaGetSymbolAddress((void**)&pZ2b, g_Z2b);
    cudaGetSymbolAddress((void**)&pdeg, g_deg);
    cudaGetSymbolAddress((void**)&pdis, g_dis);
    cudaGetSymbolAddress((void**)&pdeg2,g_deg2);
    cudaGetSymbolAddress((void**)&pdis2,g_dis2);
    cudaGetSymbolAddress((void**)&pen,  g_enorm);
    cudaGetSymbolAddress((void**)&pnnz, g_nnz);
    cudaGetSymbolAddress((void**)&psr,  g_sp_r);
    cudaGetSymbolAddress((void**)&psc,  g_sp_c);
    cudaGetSymbolAddress((void**)&psv,  g_sp_v);
    cudaGetSymbolAddress((void**)&pX3h, g_X3h);
    cudaGetSymbolAddress((void**)&pX3l, g_X3l);
    cudaGetSymbolAddress((void**)&pUh,  g_Uh);
    cudaGetSymbolAddress((void**)&pUl,  g_Ul);
    cudaGetSymbolAddress((void**)&ptDh, g_tDh);
    cudaGetSymbolAddress((void**)&ptDl, g_tDl);
    cudaGetSymbolAddress((void**)&ptSh, g_tSh);
    cudaGetSymbolAddress((void**)&ptSl, g_tSl);
    cudaGetSymbolAddress((void**)&pWfh, g_Wfh);
    cudaGetSymbolAddress((void**)&pWfl, g_Wfl);
    cudaGetSymbolAddress((void**)&pW0h, g_W0h);
    cudaGetSymbolAddress((void**)&pW0l, g_W0l);
    cudaGetSymbolAddress((void**)&pW1h, g_W1h);
    cudaGetSymbolAddress((void**)&pW1l, g_W1l);

    static cudaStream_t s2 = nullptr, s3 = nullptr;
    static cudaEvent_t evStart = nullptr, evFork = nullptr, evJoin = nullptr, evD = nullptr;
    static int attr_set = 0;
    if (!attr_set) {
        cudaFuncSetAttribute(syrk_mma_kernel,
                             cudaFuncAttributeMaxDynamicSharedMemorySize, SYRK_SMEM_DYN);
        cudaFuncSetAttribute(gemm_mma_kernel<true>,
                             cudaFuncAttributeMaxDynamicSharedMemorySize, GEMM_SMEM_DYN);
        cudaFuncSetAttribute(gemm_mma_kernel<false>,
                             cudaFuncAttributeMaxDynamicSharedMemorySize, GEMM_SMEM_DYN);
        cudaStreamCreateWithFlags(&s2, cudaStreamNonBlocking);
        cudaStreamCreateWithFlags(&s3, cudaStreamNonBlocking);
        cudaEventCreateWithFlags(&evStart, cudaEventDisableTiming);
        cudaEventCreateWithFlags(&evFork, cudaEventDisableTiming);
        cudaEventCreateWithFlags(&evJoin, cudaEventDisableTiming);
        cudaEventCreateWithFlags(&evD, cudaEventDisableTiming);
        attr_set = 1;
    }

    const int ND = n * DDIM;
    const int TPB = 256;
    dim3 blk(TPB);
    dim3 gemm_grid(DDIM / 128, (n + 127) / 128);
    const int nblk = (n + 127) / 128;
    const int ntiles = nblk * (nblk + 1) / 2;

    // ---- capture-legal fork for prep work (record on origin stream FIRST) ----
    cudaEventRecord(evStart, 0);
    cudaStreamWaitEvent(s2, evStart, 0);
    cudaStreamWaitEvent(s3, evStart, 0);

    // ---- side-stream prep (independent of U) ----
    cudaMemcpyAsync(out_emb1, emb1, (size_t)ND * sizeof(float), cudaMemcpyDeviceToDevice, s2);
    split2h_kernel<<<(LLAYERS * DDIM * DDIM + TPB - 1) / TPB, blk, 0, s2>>>(
        gnn1_W, pW1h, pW1l, LLAYERS * DDIM * DDIM);
    fill_kernel<<<(n + TPB - 1) / TPB, blk, 0, s2>>>(pdeg2, 1.0f, n);
    edge_deg_kernel<<<(E + TPB - 1) / TPB, blk, 0, s2>>>(eidx + E, eattr, pdeg2, E);
    rsqrt_kernel<<<(n + TPB - 1) / TPB, blk, 0, s2>>>(pdis2, pdeg2, n);
    enorm_kernel<<<(E + TPB - 1) / TPB, blk, 0, s2>>>(eidx, eidx + E, eattr, pdis2, pen, E);

    split2h_kernel<<<(LLAYERS * DDIM * DDIM + TPB - 1) / TPB, blk, 0, s3>>>(
        gnn0_W, pW0h, pW0l, LLAYERS * DDIM * DDIM);
    fill_kernel<<<(n + TPB - 1) / TPB, blk, 0, s3>>>(pdeg, 1.0f, n);
    zero_int_kernel<<<1, 1, 0, s3>>>(pnnz);
    fill_kernel<<<(ND + TPB - 1) / TPB, blk, 0, s3>>>(pZ2, 0.0f, ND);
    fill_kernel<<<(ND + TPB - 1) / TPB, blk, 0, s3>>>(pZ2c, 0.0f, ND);

    // ---- stream 0 prologue: gather + Wf split + fuse GEMM + U split ----
    gather_split2_kernel<<<(ND + TPB - 1) / TPB, blk>>>(emb1, demand, supply,
                                                        pX3h, pX3l, n, T);
    split2h_kernel<<<(K3 * DDIM + TPB - 1) / TPB, blk>>>(fuse_W, pWfh, pWfl, K3 * DDIM);
    gemm_mma_kernel<true><<<gemm_grid, blk, GEMM_SMEM_DYN>>>(pX3h, pX3l, pWfh, pWfl,
                                                             pU, fuse_b, n, DDIM, K3);
    split2h_kernel<<<(ND + TPB - 1) / TPB, blk>>>(pU, pUh, pUl, ND);

    // ---- fork after U ready ----
    cudaEventRecord(evFork, 0);
    cudaStreamWaitEvent(s2, evFork, 0);
    cudaStreamWaitEvent(s3, evFork, 0);

    // === stream s3: dense-branch prep (U-dependent part) ===
    cudaMemcpyAsync(ptD, pU, (size_t)ND * sizeof(float), cudaMemcpyDeviceToDevice, s3);
    gemm_mma_kernel<false><<<gemm_grid, blk, GEMM_SMEM_DYN, s3>>>(pUh, pUl, pW0h, pW0l,
                                                                  pxw, nullptr, n, DDIM, DDIM);
    cudaEventRecord(evD, s3);

    // === stream s2: sparse GCN branch ===
    cudaMemcpyAsync(ptS, pU, (size_t)ND * sizeof(float), cudaMemcpyDeviceToDevice, s2);
    for (int l = 0; l < LLAYERS; l++) {
        const __half* Ah = (l == 0) ? pUh : ptSh;
        const __half* Al = (l == 0) ? pUl : ptSl;
        gemm_mma_kernel<false><<<gemm_grid, blk, GEMM_SMEM_DYN, s2>>>(Ah, Al,
                                                                      pW1h + (size_t)l * DDIM * DDIM,
                                                                      pW1l + (size_t)l * DDIM * DDIM,
                                                                      pxwS, nullptr, n, DDIM, DDIM);
        fill_kernel<<<(ND + TPB - 1) / TPB, blk, 0, s2>>>(pZ2b, 0.0f, ND);
        {
            int blocks = (E * 32 + TPB - 1) / TPB;
            scatter_kernel<<<blocks, blk, 0, s2>>>(pxwS, eidx, eidx + E, pen, pZ2b, E, DDIM);
        }
        if (l == 0)
            sparse_combine_kernel<true><<<(ND + TPB - 1) / TPB, blk, 0, s2>>>(
                ptS, pZ2b, pxwS, pdis2, gnn1_b + (size_t)l * DDIM, n, DDIM, ptSh, ptSl);
        else
            sparse_combine_kernel<false><<<(ND + TPB - 1) / TPB, blk, 0, s2>>>(
                ptS, pZ2b, pxwS, pdis2, gnn1_b + (size_t)l * DDIM, n, DDIM, nullptr, nullptr);
    }
    cudaEventRecord(evJoin, s2);

    // === stream 0: syrk -> softmax -> dense GCN epilogue ===
    syrk_mma_kernel<<<ntiles, 256, SYRK_SMEM_DYN>>>(pUh, pUl, out_pred, n);
    cudaStreamWaitEvent((cudaStream_t)0, evD, 0);
    softmax_relu_kernel<<<n, blk>>>(out_pred, n, pnnz, psr, psc, psv, pdeg);
    rsqrt_kernel<<<(n + TPB - 1) / TPB, blk>>>(pdis, pdeg, n);

    // layer 0 (gemm prelaunched on s3)
    {
        int blocks = (MAXNNZ * 32 + TPB - 1) / TPB;
        dense_scatter_kernel<<<blocks, blk>>>(pxw, psr, psc, psv, pdis, pZ2, pnnz);
    }
    dense_combine_kernel<<<(ND + TPB - 1) / TPB, blk>>>(ptD, pZ2, pxw, pdis,
                                                        gnn0_b, n, DDIM, ptDh, ptDl);
    // layer 1 (final: fused add with sparse branch)
    gemm_mma_kernel<false><<<gemm_grid, blk, GEMM_SMEM_DYN>>>(ptDh, ptDl,
                                                              pW0h + (size_t)DDIM * DDIM,
                                                              pW0l + (size_t)DDIM * DDIM,
                                                              pxw, nullptr, n, DDIM, DDIM);
    {
        int blocks = (MAXNNZ * 32 + TPB - 1) / TPB;
        dense_scatter_kernel<<<blocks, blk>>>(pxw, psr, psc, psv, pdis, pZ2c, pnnz);
    }
    cudaStreamWaitEvent((cudaStream_t)0, evJoin, 0);
    dense_combine_add_kernel<<<(ND + TPB - 1) / TPB, blk>>>(ptD, pZ2c, pxw, pdis,
                                                            gnn0_b + DDIM, ptS,
                                                            out_skill, n, DDIM);
}

// round 16
// speedup vs baseline: 1.0265x; 1.0265x over previous
#include <cuda_runtime.h>
#include <cuda_fp16.h>
#include <math.h>
#include <stdint.h>

#define NNODE 8000
#define DDIM  256
#define K3    768
#define EMAX  256000
#define LLAYERS 2
#define PRESERVE_F 0.1f
#define MAXNNZ (4 * NNODE)   // softmax rows sum to 1 => <=4 entries/row exceed 0.2

// ---------------- scratch (static device memory) ---------------------------------
__device__ float g_U [NNODE * DDIM];
__device__ float g_tmpD[NNODE * DDIM];
__device__ float g_tmpS[NNODE * DDIM];
__device__ float g_xw [NNODE * DDIM];
__device__ float g_xwS[NNODE * DDIM];
__device__ float g_Z2 [NNODE * DDIM];
__device__ float g_Z2c[NNODE * DDIM];
__device__ float g_Z2b[NNODE * DDIM];
__device__ float g_deg [NNODE];
__device__ float g_dis [NNODE];
__device__ float g_deg2[NNODE];
__device__ float g_dis2[NNODE];
__device__ float g_enorm[EMAX];
__device__ int   g_nnz;
__device__ int   g_sp_r[MAXNNZ];
__device__ int   g_sp_c[MAXNNZ];
__device__ float g_sp_v[MAXNNZ];
// fp16 2-way splits (x = h + l, ~22 mantissa bits)
__device__ __half g_X3h[NNODE * K3];
__device__ __half g_X3l[NNODE * K3];
__device__ __half g_Uh[NNODE * DDIM];
__device__ __half g_Ul[NNODE * DDIM];
__device__ __half g_tDh[NNODE * DDIM];
__device__ __half g_tDl[NNODE * DDIM];
__device__ __half g_tSh[NNODE * DDIM];
__device__ __half g_tSl[NNODE * DDIM];
__device__ __half g_Wfh[K3 * DDIM];
__device__ __half g_Wfl[K3 * DDIM];
__device__ __half g_W0h[LLAYERS * DDIM * DDIM];
__device__ __half g_W0l[LLAYERS * DDIM * DDIM];
__device__ __half g_W1h[LLAYERS * DDIM * DDIM];
__device__ __half g_W1l[LLAYERS * DDIM * DDIM];

__device__ __forceinline__ uint32_t smem_u32(const void* p) {
    uint32_t a;
    asm("{ .reg .u64 t; cvta.to.shared.u64 t, %1; cvt.u32.u64 %0, t; }" : "=r"(a) : "l"(p));
    return a;
}

__device__ __forceinline__ void red_add_v4(float* addr, float4 v) {
    asm volatile("red.global.add.v4.f32 [%0], {%1,%2,%3,%4};"
                 :: "l"(addr), "f"(v.x), "f"(v.y), "f"(v.z), "f"(v.w) : "memory");
}

#define LDSM_X4(r0, r1, r2, r3, addr) \
    asm volatile("ldmatrix.sync.aligned.m8n8.x4.shared.b16 {%0,%1,%2,%3}, [%4];" \
                 : "=r"(r0), "=r"(r1), "=r"(r2), "=r"(r3) : "r"(addr))
#define LDSM_X2(r0, r1, addr) \
    asm volatile("ldmatrix.sync.aligned.m8n8.x2.shared.b16 {%0,%1}, [%2];" \
                 : "=r"(r0), "=r"(r1) : "r"(addr))
#define LDSM_X2_T(r0, r1, addr) \
    asm volatile("ldmatrix.sync.aligned.m8n8.x2.trans.shared.b16 {%0,%1}, [%2];" \
                 : "=r"(r0), "=r"(r1) : "r"(addr))
#define MMA_F16(c, a0, a1, a2, a3, b0, b1) \
    asm volatile("mma.sync.aligned.m16n8k16.row.col.f32.f16.f16.f32 " \
                 "{%0,%1,%2,%3}, {%4,%5,%6,%7}, {%8,%9}, {%0,%1,%2,%3};" \
                 : "+f"((c)[0]), "+f"((c)[1]), "+f"((c)[2]), "+f"((c)[3]) \
                 : "r"(a0), "r"(a1), "r"(a2), "r"(a3), "r"(b0), "r"(b1))
#define CP_ASYNC16(saddr, gptr, sz) \
    asm volatile("cp.async.cg.shared.global [%0], [%1], 16, %2;" \
                 :: "r"(saddr), "l"(gptr), "r"(sz))
#define CP_COMMIT() asm volatile("cp.async.commit_group;")
#define CP_WAIT1()  asm volatile("cp.async.wait_group 1;")
#define CP_WAIT0()  asm volatile("cp.async.wait_group 0;")

#define LDT 40
#define LDB 136

// =================== syrk: C = U @ U^T (fp16 2-split, 2-stage, 2 CTA/SM) =========
#define SYRK_TILE_ELEMS (128 * LDT)
#define SYRK_STAGE_ELEMS (4 * SYRK_TILE_ELEMS)
#define SYRK_SMEM_DYN (2 * SYRK_STAGE_ELEMS * 2)

__global__ __launch_bounds__(256, 2)
void syrk_mma_kernel(const __half* __restrict__ Uh,
                     const __half* __restrict__ Ul,
                     float* __restrict__ C, int n)
{
    extern __shared__ char smem[];
    __half* tiles = (__half*)smem;
    float* epi = (float*)smem;

    const int tid  = threadIdx.x;
    const int wid  = tid >> 5;
    const int lane = tid & 31;
    const int wm   = wid & 1;
    const int wn   = wid >> 1;
    const int group = lane >> 2;
    const int tig   = lane & 3;

    int t = blockIdx.x;
    int bi = (int)((sqrtf(8.0f * (float)t + 1.0f) - 1.0f) * 0.5f);
    while ((bi + 1) * (bi + 2) / 2 <= t) bi++;
    while (bi * (bi + 1) / 2 > t) bi--;
    int bj = t - bi * (bi + 1) / 2;
    const int m0 = bi * 128;
    const int n0 = bj * 128;

    float acc[4][4][4];
#pragma unroll
    for (int a = 0; a < 4; a++)
#pragma unroll
        for (int b = 0; b < 4; b++)
#pragma unroll
            for (int c = 0; c < 4; c++) acc[a][b][c] = 0.f;

    const __half* srcs[4] = { Uh, Ul, Uh, Ul };
    const uint32_t sT = smem_u32(tiles);

    const int a_row = (lane & 15);
    const int a_col = (lane >> 4) * 8;
    const int b_row = (lane & 7);
    const int b_col = ((lane >> 3) & 1) * 8;
    const uint32_t a_base = (uint32_t)((wm * 64 + a_row) * LDT + a_col) * 2;
    const uint32_t b_base = (uint32_t)((wn * 32 + b_row) * LDT + b_col) * 2;

    auto load_chunk = [&](int k0, int stage) {
        uint32_t dst0 = sT + (uint32_t)(stage * SYRK_STAGE_ELEMS) * 2;
#pragma unroll
        for (int s = 0; s < 4; s++) {
            const __half* src = srcs[s];
            const int rowbase = (s < 2) ? m0 : n0;
            uint32_t dts = dst0 + (uint32_t)(s * SYRK_TILE_ELEMS) * 2;
#pragma unroll
            for (int it = 0; it < 2; it++) {
                int lin = it * 256 + tid;
                int r   = lin >> 2;
                int c8  = (lin & 3) * 8;
                int g   = rowbase + r;
                uint32_t sz = (g < n) ? 16u : 0u;
                int g2 = (g < n) ? g : 0;
                const __half* gp = src + (size_t)g2 * DDIM + k0 + c8;
                CP_ASYNC16(dts + (uint32_t)(r * LDT + c8) * 2, gp, sz);
            }
        }
    };

    load_chunk(0, 0);
    CP_COMMIT();

#pragma unroll 1
    for (int kc = 0; kc < 8; kc++) {
        const int cur = kc & 1;
        if (kc + 1 < 8) {
            load_chunk((kc + 1) * 32, cur ^ 1);
            CP_COMMIT();
            CP_WAIT1();
        } else {
            CP_WAIT0();
        }
        __syncthreads();

        const uint32_t stg = sT + (uint32_t)(cur * SYRK_STAGE_ELEMS) * 2;
        const uint32_t sAh = stg;
        const uint32_t sAl = stg + SYRK_TILE_ELEMS * 2u;
        const uint32_t sBh = stg + SYRK_TILE_ELEMS * 4u;
        const uint32_t sBl = stg + SYRK_TILE_ELEMS * 6u;

#pragma unroll
        for (int ks = 0; ks < 2; ks++) {
            const uint32_t koff = (uint32_t)(ks * 16) * 2;
            uint32_t ah[4][4], bh[4][2];
#pragma unroll
            for (int mt = 0; mt < 4; mt++)
                LDSM_X4(ah[mt][0], ah[mt][1], ah[mt][2], ah[mt][3],
                        sAh + a_base + koff + (uint32_t)(mt * 16 * LDT) * 2);
#pragma unroll
            for (int nt = 0; nt < 4; nt++)
                LDSM_X2(bh[nt][0], bh[nt][1],
                        sBh + b_base + koff + (uint32_t)(nt * 8 * LDT) * 2);
#pragma unroll
            for (int mt = 0; mt < 4; mt++)
#pragma unroll
                for (int nt = 0; nt < 4; nt++)
                    MMA_F16(acc[mt][nt], ah[mt][0], ah[mt][1], ah[mt][2], ah[mt][3],
                            bh[nt][0], bh[nt][1]);
            {
                uint32_t bl[4][2];
#pragma unroll
                for (int nt = 0; nt < 4; nt++)
                    LDSM_X2(bl[nt][0], bl[nt][1],
                            sBl + b_base + koff + (uint32_t)(nt * 8 * LDT) * 2);
#pragma unroll
                for (int mt = 0; mt < 4; mt++)
#pragma unroll
                    for (int nt = 0; nt < 4; nt++)
                        MMA_F16(acc[mt][nt], ah[mt][0], ah[mt][1], ah[mt][2], ah[mt][3],
                                bl[nt][0], bl[nt][1]);
            }
            {
                uint32_t al[4][4];
#pragma unroll
                for (int mt = 0; mt < 4; mt++)
                    LDSM_X4(al[mt][0], al[mt][1], al[mt][2], al[mt][3],
                            sAl + a_base + koff + (uint32_t)(mt * 16 * LDT) * 2);
#pragma unroll
                for (int mt = 0; mt < 4; mt++)
#pragma unroll
                    for (int nt = 0; nt < 4; nt++)
                        MMA_F16(acc[mt][nt], al[mt][0], al[mt][1], al[mt][2], al[mt][3],
                                bh[nt][0], bh[nt][1]);
            }
        }
        __syncthreads();
    }

    // direct write
#pragma unroll
    for (int mt = 0; mt < 4; mt++) {
#pragma unroll
        for (int nt = 0; nt < 4; nt++) {
            int lm = wm * 64 + mt * 16 + group;
            int ln = wn * 32 + nt * 8 + tig * 2;
            int gm = m0 + lm, gn = n0 + ln;
            if (gn + 1 < n) {
                if (gm < n)
                    *reinterpret_cast<float2*>(C + (size_t)gm * n + gn) =
                        make_float2(acc[mt][nt][0], acc[mt][nt][1]);
                if (gm + 8 < n)
                    *reinterpret_cast<float2*>(C + (size_t)(gm + 8) * n + gn) =
                        make_float2(acc[mt][nt][2], acc[mt][nt][3]);
            }
        }
    }

    // mirrored write via smem transpose
    if (bi != bj) {
        __syncthreads();
#pragma unroll
        for (int mt = 0; mt < 4; mt++) {
#pragma unroll
            for (int nt = 0; nt < 4; nt++) {
                int lm = wm * 64 + mt * 16 + group;
                int ln = wn * 32 + nt * 8 + tig * 2;
                epi[lm * 129 + ln]           = acc[mt][nt][0];
                epi[lm * 129 + ln + 1]       = acc[mt][nt][1];
                epi[(lm + 8) * 129 + ln]     = acc[mt][nt][2];
                epi[(lm + 8) * 129 + ln + 1] = acc[mt][nt][3];
            }
        }
        __syncthreads();
        const int c_row = tid >> 1;
        const int half  = tid & 1;
        const int grow  = n0 + c_row;
        if (grow < n) {
            float* outrow = C + (size_t)grow * n;
#pragma unroll
            for (int i = 0; i < 16; i++) {
                int ml = half * 64 + i * 4;
                if (m0 + ml + 3 < n) {
                    float4 v = make_float4(epi[(ml + 0) * 129 + c_row],
                                           epi[(ml + 1) * 129 + c_row],
                                           epi[(ml + 2) * 129 + c_row],
                                           epi[(ml + 3) * 129 + c_row]);
                    *reinterpret_cast<float4*>(outrow + m0 + ml) = v;
                } else {
                    for (int q = 0; q < 4; q++)
                        if (m0 + ml + q < n)
                            outrow[m0 + ml + q] = epi[(ml + q) * 129 + c_row];
                }
            }
        }
    }
}

// =================== GEMM: C = A @ B (+bias), fp16 2-split, 2-stage ==============
#define GEMM_AT_ELEMS (128 * LDT)
#define GEMM_BT_ELEMS (32 * LDB)
#define GEMM_STAGE_ELEMS (2 * (GEMM_AT_ELEMS + GEMM_BT_ELEMS))
#define GEMM_SMEM_DYN (2 * GEMM_STAGE_ELEMS * 2)

template<bool BIAS, bool SPLITOUT>
__global__ __launch_bounds__(256, 2)
void gemm_mma_kernel(const __half* __restrict__ Ah_,
                     const __half* __restrict__ Al_,
                     const __half* __restrict__ Bh_,
                     const __half* __restrict__ Bl_,
                     float* __restrict__ C, const float* __restrict__ bias,
                     __half* __restrict__ Ch, __half* __restrict__ Cl,
                     int M, int N, int K)
{
    extern __shared__ char smem[];
    __half* tiles = (__half*)smem;

    const int tid  = threadIdx.x;
    const int wid  = tid >> 5;
    const int lane = tid & 31;
    const int wm   = wid & 1;
    const int wn   = wid >> 1;
    const int group = lane >> 2;
    const int tig   = lane & 3;

    const int n0 = blockIdx.x * 128;
    const int m0 = blockIdx.y * 128;

    float acc[4][4][4];
#pragma unroll
    for (int a = 0; a < 4; a++)
#pragma unroll
        for (int b = 0; b < 4; b++)
#pragma unroll
            for (int c = 0; c < 4; c++) acc[a][b][c] = 0.f;

    const __half* Asrc[2] = { Ah_, Al_ };
    const __half* Bsrc[2] = { Bh_, Bl_ };
    const uint32_t sT = smem_u32(tiles);

    const int a_row = (lane & 15);
    const int a_col = (lane >> 4) * 8;
    const uint32_t a_base = (uint32_t)((wm * 64 + a_row) * LDT + a_col) * 2;
    const uint32_t bt_base = (uint32_t)((lane & 15) * LDB + wn * 32) * 2;

    auto load_chunk = [&](int k0, int stage) {
        uint32_t dst0 = sT + (uint32_t)(stage * GEMM_STAGE_ELEMS) * 2;
#pragma unroll
        for (int s = 0; s < 2; s++) {
            uint32_t dts = dst0 + (uint32_t)(s * GEMM_AT_ELEMS) * 2;
#pragma unroll
            for (int it = 0; it < 2; it++) {
                int lin = it * 256 + tid;
                int r   = lin >> 2;
                int c8  = (lin & 3) * 8;
                int g   = m0 + r;
                uint32_t sz = (g < M) ? 16u : 0u;
                int g2 = (g < M) ? g : 0;
                const __half* gp = Asrc[s] + (size_t)g2 * K + k0 + c8;
                CP_ASYNC16(dts + (uint32_t)(r * LDT + c8) * 2, gp, sz);
            }
        }
        uint32_t dstB = dst0 + (uint32_t)(2 * GEMM_AT_ELEMS) * 2;
#pragma unroll
        for (int s = 0; s < 2; s++) {
            uint32_t dts = dstB + (uint32_t)(s * GEMM_BT_ELEMS) * 2;
#pragma unroll
            for (int it = 0; it < 2; it++) {
                int lin = it * 256 + tid;
                int r   = lin >> 4;
                int c8  = (lin & 15) * 8;
                const __half* gp = Bsrc[s] + (size_t)(k0 + r) * N + n0 + c8;
                CP_ASYNC16(dts + (uint32_t)(r * LDB + c8) * 2, gp, 16u);
            }
        }
    };

    const int NC = K / 32;
    load_chunk(0, 0);
    CP_COMMIT();

#pragma unroll 1
    for (int kc = 0; kc < NC; kc++) {
        const int cur = kc & 1;
        if (kc + 1 < NC) {
            load_chunk((kc + 1) * 32, cur ^ 1);
            CP_COMMIT();
            CP_WAIT1();
        } else {
            CP_WAIT0();
        }
        __syncthreads();

        const uint32_t stg = sT + (uint32_t)(cur * GEMM_STAGE_ELEMS) * 2;
        const uint32_t sAh = stg;
        const uint32_t sAl = stg + GEMM_AT_ELEMS * 2u;
        const uint32_t sBh = stg + GEMM_AT_ELEMS * 4u;
        const uint32_t sBl = sBh + GEMM_BT_ELEMS * 2u;

#pragma unroll
        for (int ks = 0; ks < 2; ks++) {
            const uint32_t akoff = (uint32_t)(ks * 16) * 2;
            const uint32_t bkoff = (uint32_t)(ks * 16 * LDB) * 2;
            uint32_t ah[4][4], bh[4][2];
#pragma unroll
            for (int mt = 0; mt < 4; mt++)
                LDSM_X4(ah[mt][0], ah[mt][1], ah[mt][2], ah[mt][3],
                        sAh + a_base + akoff + (uint32_t)(mt * 16 * LDT) * 2);
#pragma unroll
            for (int nt = 0; nt < 4; nt++)
                LDSM_X2_T(bh[nt][0], bh[nt][1],
                          sBh + bt_base + bkoff + (uint32_t)(nt * 8) * 2);
#pragma unroll
            for (int mt = 0; mt < 4; mt++)
#pragma unroll
                for (int nt = 0; nt < 4; nt++)
                    MMA_F16(acc[mt][nt], ah[mt][0], ah[mt][1], ah[mt][2], ah[mt][3],
                            bh[nt][0], bh[nt][1]);
            {
                uint32_t bl[4][2];
#pragma unroll
                for (int nt = 0; nt < 4; nt++)
                    LDSM_X2_T(bl[nt][0], bl[nt][1],
                              sBl + bt_base + bkoff + (uint32_t)(nt * 8) * 2);
#pragma unroll
                for (int mt = 0; mt < 4; mt++)
#pragma unroll
                    for (int nt = 0; nt < 4; nt++)
                        MMA_F16(acc[mt][nt], ah[mt][0], ah[mt][1], ah[mt][2], ah[mt][3],
                                bl[nt][0], bl[nt][1]);
            }
            {
                uint32_t al[4][4];
#pragma unroll
                for (int mt = 0; mt < 4; mt++)
                    LDSM_X4(al[mt][0], al[mt][1], al[mt][2], al[mt][3],
                            sAl + a_base + akoff + (uint32_t)(mt * 16 * LDT) * 2);
#pragma unroll
                for (int mt = 0; mt < 4; mt++)
#pragma unroll
                    for (int nt = 0; nt < 4; nt++)
                        MMA_F16(acc[mt][nt], al[mt][0], al[mt][1], al[mt][2], al[mt][3],
                                bh[nt][0], bh[nt][1]);
            }
        }
        __syncthreads();
    }

    // epilogue (optionally emit fp16 h/l splits of C straight from registers)
#pragma unroll
    for (int mt = 0; mt < 4; mt++) {
#pragma unroll
        for (int nt = 0; nt < 4; nt++) {
            int lm = wm * 64 + mt * 16 + group;
            int ln = wn * 32 + nt * 8 + tig * 2;
            int gm = m0 + lm, gn = n0 + ln;
            float b0 = 0.f, b1 = 0.f;
            if (BIAS) { b0 = bias[gn]; b1 = bias[gn + 1]; }
#pragma unroll
            for (int half = 0; half < 2; half++) {
                int row = gm + half * 8;
                if (row >= M) continue;
                float v0 = acc[mt][nt][half * 2 + 0] + b0;
                float v1 = acc[mt][nt][half * 2 + 1] + b1;
                *reinterpret_cast<float2*>(C + (size_t)row * N + gn) = make_float2(v0, v1);
                if (SPLITOUT) {
                    __half h0 = __float2half(v0);
                    __half h1 = __float2half(v1);
                    __half l0 = __float2half(v0 - __half2float(h0));
                    __half l1 = __float2half(v1 - __half2float(h1));
                    *reinterpret_cast<__half2*>(Ch + (size_t)row * N + gn) =
                        __halves2half2(h0, h1);
                    *reinterpret_cast<__half2*>(Cl + (size_t)row * N + gn) =
                        __halves2half2(l0, l1);
                }
            }
        }
    }
}

// ---------------- split kernels (fp16 2-way) --------------------------------------
__global__ void split2h_kernel(const float* __restrict__ U,
                               __half* __restrict__ Uh,
                               __half* __restrict__ Ul, int total)
{
    int i = blockIdx.x * blockDim.x + threadIdx.x;
    if (i >= total) return;
    float x = U[i];
    __half h = __float2half(x);
    Uh[i] = h;
    Ul[i] = __float2half(x - __half2float(h));
}

__global__ void gather_split2_kernel(const float* __restrict__ emb1,
                                     const float* __restrict__ demand,
                                     const float* __restrict__ supply,
                                     __half* __restrict__ Xh,
                                     __half* __restrict__ Xl, int n, int T)
{
    int i = blockIdx.x * blockDim.x + threadIdx.x;
    int total = n * DDIM;
    if (i >= total) return;
    int node = i / DDIM, d = i % DDIM;
    float v[3];
    v[0] = emb1[(size_t)node * DDIM + d];
    v[1] = demand[((size_t)node * T + (T - 1)) * DDIM + d];
    v[2] = supply[((size_t)node * T + (T - 1)) * DDIM + d];
#pragma unroll
    for (int s = 0; s < 3; s++) {
        size_t idx = (size_t)node * K3 + s * DDIM + d;
        float x = v[s];
        __half h = __float2half(x);
        Xh[idx] = h;
        Xl[idx] = __float2half(x - __half2float(h));
    }
}

// ---------------- small kernels ---------------------------------------------------
__global__ void softmax_relu_kernel(float* __restrict__ Z, int n,
                                    int* __restrict__ nnz,
                                    int* __restrict__ sr, int* __restrict__ sc,
                                    float* __restrict__ sv,
                                    float* __restrict__ deg)
{
    __shared__ float row[NNODE];
    __shared__ float red[256];
    int r = blockIdx.x;
    int t = threadIdx.x;
    float* zr = Z + (size_t)r * n;
    const int n4 = n >> 2;

    float mx = -3.4e38f;
    for (int c4 = t; c4 < n4; c4 += 256) {
        float4 v = reinterpret_cast<const float4*>(zr)[c4];
        reinterpret_cast<float4*>(row)[c4] = v;
        mx = fmaxf(mx, fmaxf(fmaxf(v.x, v.y), fmaxf(v.z, v.w)));
    }
    for (int c = n4 * 4 + t; c < n; c += 256) { float v = zr[c]; row[c] = v; mx = fmaxf(mx, v); }
    red[t] = mx; __syncthreads();
    for (int s = 128; s > 0; s >>= 1) {
        if (t < s) red[t] = fmaxf(red[t], red[t + s]);
        __syncthreads();
    }
    mx = red[0];
    __syncthreads();

    float sm = 0.f;
    for (int c4 = t; c4 < n4; c4 += 256) {
        float4 v = reinterpret_cast<const float4*>(row)[c4];
        v.x = __expf(v.x - mx); v.y = __expf(v.y - mx);
        v.z = __expf(v.z - mx); v.w = __expf(v.w - mx);
        reinterpret_cast<float4*>(row)[c4] = v;
        sm += v.x + v.y + v.z + v.w;
    }
    for (int c = n4 * 4 + t; c < n; c += 256) { float e = __expf(row[c] - mx); row[c] = e; sm += e; }
    red[t] = sm; __syncthreads();
    for (int s = 128; s > 0; s >>= 1) {
        if (t < s) red[t] += red[t + s];
        __syncthreads();
    }
    float inv = 1.0f / red[0];
    for (int c4 = t; c4 < n4; c4 += 256) {
        float4 v = reinterpret_cast<const float4*>(row)[c4];
        float4 p;
        p.x = fmaxf(v.x * inv - 0.2f, 0.f);
        p.y = fmaxf(v.y * inv - 0.2f, 0.f);
        p.z = fmaxf(v.z * inv - 0.2f, 0.f);
        p.w = fmaxf(v.w * inv - 0.2f, 0.f);
        reinterpret_cast<float4*>(zr)[c4] = p;
        float pv[4] = { p.x, p.y, p.z, p.w };
#pragma unroll
        for (int q = 0; q < 4; q++) {
            if (pv[q] > 0.f) {
                int c = c4 * 4 + q;
                int idx = atomicAdd(nnz, 1);
                if (idx < MAXNNZ) { sr[idx] = r; sc[idx] = c; sv[idx] = pv[q]; }
                atomicAdd(&deg[c], pv[q]);
            }
        }
    }
    for (int c = n4 * 4 + t; c < n; c += 256) {
        float p = fmaxf(row[c] * inv - 0.2f, 0.f);
        zr[c] = p;
        if (p > 0.f) {
            int idx = atomicAdd(nnz, 1);
            if (idx < MAXNNZ) { sr[idx] = r; sc[idx] = c; sv[idx] = p; }
            atomicAdd(&deg[c], p);
        }
    }
}

__global__ void fill_kernel(float* p, float v, int n)
{
    int i = blockIdx.x * blockDim.x + threadIdx.x;
    if (i < n) p[i] = v;
}

__global__ void zero_int_kernel(int* p) { *p = 0; }

__global__ void rsqrt_kernel(float* __restrict__ dst, const float* __restrict__ src, int n)
{
    int i = blockIdx.x * blockDim.x + threadIdx.x;
    if (i < n) dst[i] = rsqrtf(src[i]);
}

__global__ void dense_scatter_kernel(const float* __restrict__ xw,
                                     const int* __restrict__ sr,
                                     const int* __restrict__ sc,
                                     const float* __restrict__ sv,
                                     const float* __restrict__ dis,
                                     float* __restrict__ agg,
                                     const int* __restrict__ nnz)
{
    int warp = (blockIdx.x * blockDim.x + threadIdx.x) >> 5;
    int lane = threadIdx.x & 31;
    int m = *nnz; if (m > MAXNNZ) m = MAXNNZ;
    if (warp >= m) return;
    int r = sr[warp], c = sc[warp];
    float w = sv[warp] * dis[r];
    const float4* xr = reinterpret_cast<const float4*>(xw + (size_t)r * DDIM);
    float* ar = agg + (size_t)c * DDIM;
#pragma unroll
    for (int h = 0; h < 2; h++) {
        int f4 = h * 32 + lane;
        float4 x = xr[f4];
        red_add_v4(ar + f4 * 4, make_float4(w * x.x, w * x.y, w * x.z, w * x.w));
    }
}

// dense combine, intermediate layer: temp (in-place) + fp16 split emission
__global__ void dense_combine_kernel(float* __restrict__ temp, const float* __restrict__ Z2,
                                     const float* __restrict__ xw, const float* __restrict__ dis,
                                     const float* __restrict__ b, int n, int d,
                                     __half* __restrict__ th,
                                     __half* __restrict__ tl)
{
    int i = blockIdx.x * blockDim.x + threadIdx.x;
    if (i >= n * d) return;
    int c = i / d, dd = i - c * d;
    float s = dis[c];
    float out = s * Z2[i] + s * s * xw[i] + b[dd];
    float v = (1.0f - PRESERVE_F) * out + PRESERVE_F * temp[i];
    temp[i] = v;
    __half h = __float2half(v);
    th[i] = h; tl[i] = __float2half(v - __half2float(h));
}

// dense combine, FINAL layer: fuse out_skill = v + tmpS
__global__ void dense_combine_add_kernel(const float* __restrict__ temp,
                                         const float* __restrict__ Z2,
                                         const float* __restrict__ xw,
                                         const float* __restrict__ dis,
                                         const float* __restrict__ b,
                                         const float* __restrict__ tmpS,
                                         float* __restrict__ out, int n, int d)
{
    int i = blockIdx.x * blockDim.x + threadIdx.x;
    if (i >= n * d) return;
    int c = i / d, dd = i - c * d;
    float s = dis[c];
    float o = s * Z2[i] + s * s * xw[i] + b[dd];
    float v = (1.0f - PRESERVE_F) * o + PRESERVE_F * temp[i];
    out[i] = v + tmpS[i];
}

__global__ void edge_deg_kernel(const int* __restrict__ dst, const float* __restrict__ attr,
                                float* __restrict__ deg2, int E)
{
    int e = blockIdx.x * blockDim.x + threadIdx.x;
    if (e < E) atomicAdd(&deg2[dst[e]], attr[e]);
}

__global__ void enorm_kernel(const int* __restrict__ src, const int* __restrict__ dst,
                             const float* __restrict__ attr, const float* __restrict__ dis2,
                             float* __restrict__ enorm, int E)
{
    int e = blockIdx.x * blockDim.x + threadIdx.x;
    if (e < E) enorm[e] = dis2[src[e]] * attr[e] * dis2[dst[e]];
}

__global__ void scatter_kernel(const float* __restrict__ xw, const int* __restrict__ src,
                               const int* __restrict__ dst, const float* __restrict__ enorm,
                               float* __restrict__ agg, int E, int d)
{
    int warp = (blockIdx.x * blockDim.x + threadIdx.x) >> 5;
    int lane = threadIdx.x & 31;
    if (warp >= E) return;
    int s = src[warp], t = dst[warp];
    float w = enorm[warp];
    const float4* xr = reinterpret_cast<const float4*>(xw + (size_t)s * DDIM);
    float* ar = agg + (size_t)t * DDIM;
#pragma unroll
    for (int h = 0; h < 2; h++) {
        int f4 = h * 32 + lane;
        float4 x = xr[f4];
        red_add_v4(ar + f4 * 4, make_float4(w * x.x, w * x.y, w * x.z, w * x.w));
    }
}

template<bool EMIT>
__global__ void sparse_combine_kernel(float* __restrict__ temp, const float* __restrict__ agg,
                                      const float* __restrict__ xw, const float* __restrict__ dis2,
                                      const float* __restrict__ b, int n, int d,
                                      __half* __restrict__ th,
                                      __half* __restrict__ tl)
{
    int i = blockIdx.x * blockDim.x + threadIdx.x;
    if (i >= n * d) return;
    int c = i / d, dd = i - c * d;
    float s = dis2[c];
    float out = agg[i] + s * s * xw[i] + b[dd];
    float v = (1.0f - PRESERVE_F) * out + PRESERVE_F * temp[i];
    temp[i] = v;
    if (EMIT) {
        __half h = __float2half(v);
        th[i] = h; tl[i] = __float2half(v - __half2float(h));
    }
}

// ---------------- host orchestration ----------------------------------------------
extern "C" void kernel_launch(void* const* d_in, const int* in_sizes, int n_in,
                              void* d_out, int out_size)
{
    const float* demand  = (const float*)d_in[0];
    const float* supply  = (const float*)d_in[1];
    const int*   eidx    = (const int*)  d_in[2];
    const float* eattr   = (const float*)d_in[3];
    const float* emb1    = (const float*)d_in[4];
    const float* fuse_W  = (const float*)d_in[5];
    const float* fuse_b  = (const float*)d_in[6];
    const float* gnn0_W  = (const float*)d_in[7];
    const float* gnn0_b  = (const float*)d_in[8];
    const float* gnn1_W  = (const float*)d_in[9];
    const float* gnn1_b  = (const float*)d_in[10];

    const int n = in_sizes[4] / DDIM;
    const int E = in_sizes[3];
    const int T = in_sizes[0] / (n * DDIM);

    float* out_emb1  = (float*)d_out;
    float* out_skill = out_emb1 + (size_t)n * DDIM;
    float* out_pred  = out_skill + (size_t)n * DDIM;

    float *pU, *ptD, *ptS, *pxw, *pxwS, *pZ2, *pZ2c, *pZ2b, *pdeg, *pdis, *pdeg2, *pdis2, *pen, *psv;
    int *pnnz, *psr, *psc;
    __half *pX3h, *pX3l, *pUh, *pUl, *ptDh, *ptDl, *ptSh, *ptSl;
    __half *pWfh, *pWfl, *pW0h, *pW0l, *pW1h, *pW1l;
    cudaGetSymbolAddress((void**)&pU,   g_U);
    cudaGetSymbolAddress((void**)&ptD,  g_tmpD);
    cudaGetSymbolAddress((void**)&ptS,  g_tmpS);
    cudaGetSymbolAddress((void**)&pxw,  g_xw);
    cudaGetSymbolAddress((void**)&pxwS, g_xwS);
    cudaGetSymbolAddress((void**)&pZ2,  g_Z2);
    cudaGetSymbolAddress((void**)&pZ2c, g_Z2c);
    cudaGetSymbolAddress((void**)&pZ2b, g_Z2b);
    cudaGetSymbolAddress((void**)&pdeg, g_deg);
    cudaGetSymbolAddress((void**)&pdis, g_dis);
    cudaGetSymbolAddress((void**)&pdeg2,g_deg2);
    cudaGetSymbolAddress((void**)&pdis2,g_dis2);
    cudaGetSymbolAddress((void**)&pen,  g_enorm);
    cudaGetSymbolAddress((void**)&pnnz, g_nnz);
    cudaGetSymbolAddress((void**)&psr,  g_sp_r);
    cudaGetSymbolAddress((void**)&psc,  g_sp_c);
    cudaGetSymbolAddress((void**)&psv,  g_sp_v);
    cudaGetSymbolAddress((void**)&pX3h, g_X3h);
    cudaGetSymbolAddress((void**)&pX3l, g_X3l);
    cudaGetSymbolAddress((void**)&pUh,  g_Uh);
    cudaGetSymbolAddress((void**)&pUl,  g_Ul);
    cudaGetSymbolAddress((void**)&ptDh, g_tDh);
    cudaGetSymbolAddress((void**)&ptDl, g_tDl);
    cudaGetSymbolAddress((void**)&ptSh, g_tSh);
    cudaGetSymbolAddress((void**)&ptSl, g_tSl);
    cudaGetSymbolAddress((void**)&pWfh, g_Wfh);
    cudaGetSymbolAddress((void**)&pWfl, g_Wfl);
    cudaGetSymbolAddress((void**)&pW0h, g_W0h);
    cudaGetSymbolAddress((void**)&pW0l, g_W0l);
    cudaGetSymbolAddress((void**)&pW1h, g_W1h);
    cudaGetSymbolAddress((void**)&pW1l, g_W1l);

    static cudaStream_t s2 = nullptr, s3 = nullptr;
    static cudaEvent_t evFork = nullptr, evJoin = nullptr, evD = nullptr;
    static int attr_set = 0;
    if (!attr_set) {
        cudaFuncSetAttribute(syrk_mma_kernel,
                             cudaFuncAttributeMaxDynamicSharedMemorySize, SYRK_SMEM_DYN);
        cudaFuncSetAttribute(gemm_mma_kernel<true, true>,
                             cudaFuncAttributeMaxDynamicSharedMemorySize, GEMM_SMEM_DYN);
        cudaFuncSetAttribute(gemm_mma_kernel<false, false>,
                             cudaFuncAttributeMaxDynamicSharedMemorySize, GEMM_SMEM_DYN);
        cudaStreamCreateWithFlags(&s2, cudaStreamNonBlocking);
        cudaStreamCreateWithFlags(&s3, cudaStreamNonBlocking);
        cudaEventCreateWithFlags(&evFork, cudaEventDisableTiming);
        cudaEventCreateWithFlags(&evJoin, cudaEventDisableTiming);
        cudaEventCreateWithFlags(&evD, cudaEventDisableTiming);
        attr_set = 1;
    }

    const int ND = n * DDIM;
    const int TPB = 256;
    dim3 blk(TPB);
    dim3 gemm_grid(DDIM / 128, (n + 127) / 128);
    const int nblk = (n + 127) / 128;
    const int ntiles = nblk * (nblk + 1) / 2;

    // ---- prologue (stream 0): splits + fuse GEMM (emits U + Uh/Ul directly) ----
    gather_split2_kernel<<<(ND + TPB - 1) / TPB, blk>>>(emb1, demand, supply,
                                                        pX3h, pX3l, n, T);
    split2h_kernel<<<(K3 * DDIM + TPB - 1) / TPB, blk>>>(fuse_W, pWfh, pWfl, K3 * DDIM);
    split2h_kernel<<<(LLAYERS * DDIM * DDIM + TPB - 1) / TPB, blk>>>(gnn0_W, pW0h, pW0l,
                                                                     LLAYERS * DDIM * DDIM);
    split2h_kernel<<<(LLAYERS * DDIM * DDIM + TPB - 1) / TPB, blk>>>(gnn1_W, pW1h, pW1l,
                                                                     LLAYERS * DDIM * DDIM);
    cudaMemcpyAsync(out_emb1, emb1, (size_t)ND * sizeof(float), cudaMemcpyDeviceToDevice);

    gemm_mma_kernel<true, true><<<gemm_grid, blk, GEMM_SMEM_DYN>>>(
        pX3h, pX3l, pWfh, pWfl, pU, fuse_b, pUh, pUl, n, DDIM, K3);

    // ---- fork ----
    cudaEventRecord(evFork, 0);
    cudaStreamWaitEvent(s2, evFork, 0);
    cudaStreamWaitEvent(s3, evFork, 0);

    // === stream s3: dense-branch prep ===
    cudaMemcpyAsync(ptD, pU, (size_t)ND * sizeof(float), cudaMemcpyDeviceToDevice, s3);
    fill_kernel<<<(n + TPB - 1) / TPB, blk, 0, s3>>>(pdeg, 1.0f, n);
    zero_int_kernel<<<1, 1, 0, s3>>>(pnnz);
    fill_kernel<<<(ND + TPB - 1) / TPB, blk, 0, s3>>>(pZ2, 0.0f, ND);
    fill_kernel<<<(ND + TPB - 1) / TPB, blk, 0, s3>>>(pZ2c, 0.0f, ND);
    gemm_mma_kernel<false, false><<<gemm_grid, blk, GEMM_SMEM_DYN, s3>>>(
        pUh, pUl, pW0h, pW0l, pxw, nullptr, nullptr, nullptr, n, DDIM, DDIM);
    cudaEventRecord(evD, s3);

    // === stream s2: sparse GCN branch ===
    cudaMemcpyAsync(ptS, pU, (size_t)ND * sizeof(float), cudaMemcpyDeviceToDevice, s2);
    fill_kernel<<<(n + TPB - 1) / TPB, blk, 0, s2>>>(pdeg2, 1.0f, n);
    edge_deg_kernel<<<(E + TPB - 1) / TPB, blk, 0, s2>>>(eidx + E, eattr, pdeg2, E);
    rsqrt_kernel<<<(n + TPB - 1) / TPB, blk, 0, s2>>>(pdis2, pdeg2, n);
    enorm_kernel<<<(E + TPB - 1) / TPB, blk, 0, s2>>>(eidx, eidx + E, eattr, pdis2, pen, E);
    for (int l = 0; l < LLAYERS; l++) {
        const __half* Ah = (l == 0) ? pUh : ptSh;
        const __half* Al = (l == 0) ? pUl : ptSl;
        gemm_mma_kernel<false, false><<<gemm_grid, blk, GEMM_SMEM_DYN, s2>>>(
            Ah, Al, pW1h + (size_t)l * DDIM * DDIM, pW1l + (size_t)l * DDIM * DDIM,
            pxwS, nullptr, nullptr, nullptr, n, DDIM, DDIM);
        fill_kernel<<<(ND + TPB - 1) / TPB, blk, 0, s2>>>(pZ2b, 0.0f, ND);
        {
            int blocks = (E * 32 + TPB - 1) / TPB;
            scatter_kernel<<<blocks, blk, 0, s2>>>(pxwS, eidx, eidx + E, pen, pZ2b, E, DDIM);
        }
        if (l == 0)
            sparse_combine_kernel<true><<<(ND + TPB - 1) / TPB, blk, 0, s2>>>(
                ptS, pZ2b, pxwS, pdis2, gnn1_b + (size_t)l * DDIM, n, DDIM, ptSh, ptSl);
        else
            sparse_combine_kernel<false><<<(ND + TPB - 1) / TPB, blk, 0, s2>>>(
                ptS, pZ2b, pxwS, pdis2, gnn1_b + (size_t)l * DDIM, n, DDIM, nullptr, nullptr);
    }
    cudaEventRecord(evJoin, s2);

    // === stream 0: syrk -> softmax -> dense GCN epilogue ===
    syrk_mma_kernel<<<ntiles, 256, SYRK_SMEM_DYN>>>(pUh, pUl, out_pred, n);
    cudaStreamWaitEvent((cudaStream_t)0, evD, 0);
    softmax_relu_kernel<<<n, blk>>>(out_pred, n, pnnz, psr, psc, psv, pdeg);
    rsqrt_kernel<<<(n + TPB - 1) / TPB, blk>>>(pdis, pdeg, n);

    // layer 0 (gemm prelaunched on s3)
    {
        int blocks = (MAXNNZ * 32 + TPB - 1) / TPB;
        dense_scatter_kernel<<<blocks, blk>>>(pxw, psr, psc, psv, pdis, pZ2, pnnz);
    }
    dense_combine_kernel<<<(ND + TPB - 1) / TPB, blk>>>(ptD, pZ2, pxw, pdis,
                                                        gnn0_b, n, DDIM, ptDh, ptDl);
    // layer 1 (final: fused add with sparse branch)
    gemm_mma_kernel<false, false><<<gemm_grid, blk, GEMM_SMEM_DYN>>>(
        ptDh, ptDl, pW0h + (size_t)DDIM * DDIM, pW0l + (size_t)DDIM * DDIM,
        pxw, nullptr, nullptr, nullptr, n, DDIM, DDIM);
    {
        int blocks = (MAXNNZ * 32 + TPB - 1) / TPB;
        dense_scatter_kernel<<<blocks, blk>>>(pxw, psr, psc, psv, pdis, pZ2c, pnnz);
    }
    cudaStreamWaitEvent((cudaStream_t)0, evJoin, 0);
    dense_combine_add_kernel<<<(ND + TPB - 1) / TPB, blk>>>(ptD, pZ2c, pxw, pdis,
                                                            gnn0_b + DDIM, ptS,
                                                            out_skill, n, DDIM);
}